// round 12
// baseline (speedup 1.0000x reference)
#include <cuda_runtime.h>
#include <cuda_fp16.h>
#include <cstdint>
#include <math.h>

#define NTOK   8192
#define DMODEL 1024
#define DFFE   512
#define NEXP   16
#define DFFS   1024

// ---------------- scratch (device globals; no allocations) ----------------
__device__ int   d_cnt[NEXP];
__device__ int   d_lists[NEXP * NTOK];
__device__ float d_gw[2 * NTOK];
__device__ float d_ypart[(size_t)2 * NTOK * DMODEL];   // routed partials (fp32)
// fp16 operands
__device__ __half d_hx [(size_t)NTOK * DMODEL];
__device__ __half d_w1h[(size_t)NEXP * DFFE * DMODEL];
__device__ __half d_w3h[(size_t)NEXP * DFFE * DMODEL];
__device__ __half d_w2h[(size_t)NEXP * DMODEL * DFFE];
__device__ __half d_sw1h[(size_t)DFFS * DMODEL];
__device__ __half d_sw3h[(size_t)DFFS * DMODEL];
__device__ __half d_sw2h[(size_t)DMODEL * DFFS];
__device__ __half d_h [(size_t)2 * NTOK * DFFE];       // routed hidden (fp16)
__device__ __half d_hs[(size_t)NTOK * DFFS];           // shared hidden (fp16)

__device__ __forceinline__ float fsigmoid(float v) { return 1.f / (1.f + __expf(-v)); }
__device__ __forceinline__ uint32_t smem_u32(const void* p) {
    uint32_t a;
    asm("{ .reg .u64 t; cvta.to.shared.u64 t, %1; cvt.u32.u64 %0, t; }" : "=r"(a) : "l"(p));
    return a;
}
__device__ __forceinline__ void mma_f16(float* c, const uint32_t* a, uint32_t b0, uint32_t b1) {
    asm volatile("mma.sync.aligned.m16n8k16.row.col.f32.f16.f16.f32 "
        "{%0,%1,%2,%3}, {%4,%5,%6,%7}, {%8,%9}, {%0,%1,%2,%3};"
        : "+f"(c[0]), "+f"(c[1]), "+f"(c[2]), "+f"(c[3])
        : "r"(a[0]), "r"(a[1]), "r"(a[2]), "r"(a[3]), "r"(b0), "r"(b1));
}
__device__ __forceinline__ void ldsm4(uint32_t* r, uint32_t addr) {
    asm volatile("ldmatrix.sync.aligned.m8n8.x4.shared.b16 {%0,%1,%2,%3}, [%4];"
        : "=r"(r[0]), "=r"(r[1]), "=r"(r[2]), "=r"(r[3]) : "r"(addr));
}
__device__ __forceinline__ void cp_async16(uint32_t dst, const void* src) {
    asm volatile("cp.async.cg.shared.global [%0], [%1], 16;" :: "r"(dst), "l"(src));
}
__device__ __forceinline__ uint4 pack_h8(float4 u, float4 v) {
    uint4 o;
    half2 h0 = __floats2half2_rn(u.x, u.y);
    half2 h1 = __floats2half2_rn(u.z, u.w);
    half2 h2 = __floats2half2_rn(v.x, v.y);
    half2 h3 = __floats2half2_rn(v.z, v.w);
    o.x = *(uint32_t*)&h0; o.y = *(uint32_t*)&h1;
    o.z = *(uint32_t*)&h2; o.w = *(uint32_t*)&h3;
    return o;
}

// ---------------- smem layout ----------------
// BK=64 halfs (128B data/row), row stride 144B (LDSM conflict-free: 8x36w mod 32).
// Per stage: A tile 128 rows @ +0, B tile 256 rows @ +18432. 3 stages.
#define BK       64
#define RS       144
#define NSTAGE   3
#define A_ROWS   128
#define B_ROWS   256
#define ABYTES   (A_ROWS * RS)                 // 18432
#define SSTR     ((A_ROWS + B_ROWS) * RS)      // 55296
#define SLOT_OFF (NSTAGE * SSTR)               // 165888
#define BIAS_OFF (SLOT_OFF + 512)              // 166400 (256 floats)
#define SMEM_TOTAL (BIAS_OFF + 1024)           // 167424

// ---------------- small kernels ----------------
__global__ void zero_cnt_kernel() {
    if (threadIdx.x < NEXP) d_cnt[threadIdx.x] = 0;
}

struct F2HArgs {
    const float* src[7];
    __half*      dst[7];
    int          blk_end[7];
};
__global__ void f2h_all_kernel(F2HArgs args) {
    int b = blockIdx.x;
    int seg = 0;
#pragma unroll
    for (int s = 0; s < 7; s++) if (b >= args.blk_end[s]) seg = s + 1;
    int b0 = (seg == 0) ? 0 : args.blk_end[seg - 1];
    size_t i = ((size_t)(b - b0) * blockDim.x + threadIdx.x) * 8;
    const float* src = args.src[seg];
    __half* dst = args.dst[seg];
    float4 a = *(const float4*)(src + i);
    float4 v = *(const float4*)(src + i + 4);
    *(uint4*)(dst + i) = pack_h8(a, v);
}

__global__ void gate_kernel(const float* __restrict__ x,
                            const float* __restrict__ gw,
                            const float* __restrict__ ebias)
{
    int warp = (blockIdx.x * blockDim.x + threadIdx.x) >> 5;
    int lane = threadIdx.x & 31;
    if (warp >= NTOK) return;
    const float* xr = x + (size_t)warp * DMODEL;
    float xv[32];
#pragma unroll
    for (int j = 0; j < 32; j++) xv[j] = xr[lane + 32 * j];
    float logits[NEXP];
#pragma unroll
    for (int e = 0; e < NEXP; e++) {
        const float* wr = gw + e * DMODEL;
        float acc = 0.f;
#pragma unroll
        for (int j = 0; j < 32; j++) acc += xv[j] * wr[lane + 32 * j];
#pragma unroll
        for (int o = 16; o > 0; o >>= 1) acc += __shfl_xor_sync(0xffffffffu, acc, o);
        logits[e] = acc;
    }
    if (lane == 0) {
        int i0 = -1, i1 = -1;
        float v0 = -INFINITY, v1 = -INFINITY;
#pragma unroll
        for (int e = 0; e < NEXP; e++) {
            float b = logits[e] + ebias[e];
            if (b > v0) { v1 = v0; i1 = i0; v0 = b; i0 = e; }
            else if (b > v1) { v1 = b; i1 = e; }
        }
        float s0 = fsigmoid(logits[i0]);
        float s1 = fsigmoid(logits[i1]);
        float inv = 1.f / (s0 + s1 + 1e-10f);
        int p0 = atomicAdd(&d_cnt[i0], 1);
        d_lists[i0 * NTOK + p0] = warp * 2 + 0;
        d_gw[warp * 2 + 0] = s0 * inv;
        int p1 = atomicAdd(&d_cnt[i1], 1);
        d_lists[i1 * NTOK + p1] = warp * 2 + 1;
        d_gw[warp * 2 + 1] = s1 * inv;
    }
}

// ============ fused stage-1: 128m x 128h, dual-B (256 rows) + SwiGLU ============
// B smem row r: block = r>>5 (0..7); wn_r = block>>1; W3 if (block&1); sub = r&31.
//   -> W1/W3 row (n0h + wn_r*32 + sub).
// Warp wn (0..3) covers B rows [wn*64, wn*64+64): frags 0..3 = W1, 4..7 = W3 of
// the same 32 h-cols [n0h + wn*32, +32). Warp wm (0..1): 64 m-rows.
template<int GATHER>
__global__ void __launch_bounds__(256)
gemm_dual(const __half* __restrict__ A,
          const __half* __restrict__ W1b, const __half* __restrict__ W3b,
          const float* __restrict__ b1b, const float* __restrict__ b3b,
          __half* __restrict__ Out, int K, int NW, int ldo)
{
    int e   = blockIdx.z;
    int m0  = blockIdx.y * 128;
    int n0h = blockIdx.x * 128;
    int Mv = NTOK;
    const int* list = d_lists + e * NTOK;
    if (GATHER != 0) { Mv = d_cnt[e]; if (m0 >= Mv) return; }
    const __half* W1 = W1b + (size_t)e * NW * K;
    const __half* W3 = W3b + (size_t)e * NW * K;

    extern __shared__ char smem[];
    uint32_t sbase = smem_u32(smem);
    int*   sslot = (int*)(smem + SLOT_OFF);
    float* sB1   = (float*)(smem + BIAS_OFF);
    float* sB3   = sB1 + 128;

    int tid = threadIdx.x;
    if (tid < 128) {
        int m = m0 + tid;
        sslot[tid] = (GATHER != 0) ? list[m < Mv ? m : Mv - 1] : m;
    } else {
        int j = tid - 128;
        sB1[j] = b1b[(size_t)e * NW + n0h + j];
        sB3[j] = b3b[(size_t)e * NW + n0h + j];
    }
    __syncthreads();

    // A loader: 4 chunks (128 rows x 8 chunks / 256 thr); gathered -> pointer array
    const __half* aSrc[4];
    int aRow0 = tid >> 3, cA = tid & 7;
#pragma unroll
    for (int i = 0; i < 4; i++) {
        int row = aRow0 + i * 32;
        int slot = sslot[row];
        int ar = (GATHER == 1) ? (slot >> 1) : slot;
        aSrc[i] = A + (size_t)ar * K + cA * 8;
    }
    uint32_t dstA0 = (uint32_t)(aRow0 * RS + cA * 16);
    // B loader: 8 chunks (256 rows); interleaved W1/W3 -> pointer array
    const __half* bSrc[8];
#pragma unroll
    for (int i = 0; i < 8; i++) {
        int row = aRow0 + i * 32;               // 0..255
        int blk = row >> 5, sub = row & 31;
        int wn_r = blk >> 1;
        const __half* Wsel = (blk & 1) ? W3 : W1;
        bSrc[i] = Wsel + (size_t)(n0h + wn_r * 32 + sub) * K + cA * 8;
    }
    uint32_t dstB0 = (uint32_t)(ABYTES + aRow0 * RS + cA * 16);

    int wid = tid >> 5, lane = tid & 31;
    int wm = wid & 1, wn = wid >> 1;
    int lr = lane >> 2, lc = lane & 3;
    int mat = lane >> 3, rr = lane & 7;

    uint32_t aOff[4], bOff[4];
#pragma unroll
    for (int mf = 0; mf < 4; mf++)
        aOff[mf] = (uint32_t)((wm * 64 + mf * 16 + (mat & 1) * 8 + rr) * RS + (mat >> 1) * 16);
#pragma unroll
    for (int fp = 0; fp < 4; fp++)
        bOff[fp] = (uint32_t)(ABYTES + (wn * 64 + fp * 16 + (mat >> 1) * 8 + rr) * RS + (mat & 1) * 16);

    float acc[4][8][4] = {};
    int T = K / BK;

    auto issue_tile = [&](int t) {
        uint32_t sb = sbase + (t % NSTAGE) * SSTR;
        int k0 = t * BK;
#pragma unroll
        for (int i = 0; i < 4; i++)
            cp_async16(sb + dstA0 + i * 32 * RS, aSrc[i] + k0);
#pragma unroll
        for (int i = 0; i < 8; i++)
            cp_async16(sb + dstB0 + i * 32 * RS, bSrc[i] + k0);
        asm volatile("cp.async.commit_group;" ::: "memory");
    };

    issue_tile(0);
    issue_tile(1);

    for (int t = 0; t < T; t++) {
        asm volatile("cp.async.wait_group 1;" ::: "memory");
        __syncthreads();
        uint32_t sb = sbase + (t % NSTAGE) * SSTR;
#pragma unroll
        for (int kk = 0; kk < 4; kk++) {
            uint32_t koff = kk * 32;
            uint32_t a[4][4];
#pragma unroll
            for (int mf = 0; mf < 4; mf++) ldsm4(a[mf], sb + aOff[mf] + koff);
#pragma unroll
            for (int fp = 0; fp < 4; fp++) {
                uint32_t b[4];
                ldsm4(b, sb + bOff[fp] + koff);
#pragma unroll
                for (int mf = 0; mf < 4; mf++) {
                    mma_f16(acc[mf][2 * fp],     a[mf], b[0], b[1]);
                    mma_f16(acc[mf][2 * fp + 1], a[mf], b[2], b[3]);
                }
            }
        }
        if (t + 2 < T) {
            issue_tile(t + 2);
        } else {
            asm volatile("cp.async.commit_group;" ::: "memory");
        }
    }

    // SwiGLU epilogue: frag f (0..3) = g of h-col wn*32+8f; frag f+4 = u same col
#pragma unroll
    for (int mf = 0; mf < 4; mf++) {
#pragma unroll
        for (int half = 0; half < 2; half++) {
            int rt = wm * 64 + mf * 16 + half * 8 + lr;
            int m = m0 + rt;
            if (GATHER != 0 && m >= Mv) continue;
            int orow = sslot[rt];
#pragma unroll
            for (int f = 0; f < 4; f++) {
                int nl = wn * 32 + 8 * f + 2 * lc;
                float g0 = acc[mf][f][half * 2 + 0] + sB1[nl];
                float g1 = acc[mf][f][half * 2 + 1] + sB1[nl + 1];
                float u0 = acc[mf][f + 4][half * 2 + 0] + sB3[nl];
                float u1 = acc[mf][f + 4][half * 2 + 1] + sB3[nl + 1];
                float h0 = g0 * fsigmoid(g0) * u0;
                float h1 = g1 * fsigmoid(g1) * u1;
                *(half2*)(Out + (size_t)orow * ldo + n0h + nl) = __floats2half2_rn(h0, h1);
            }
        }
    }
}

// ---------------- stage-2: 128m x 256n fp16 GEMM ----------------
// GATHER: 0 dense, 2 gather slot
// EPI: 1 (acc+b)*gw -> ypart(f32); 2 acc+b+ypart2 -> out(f32)
template<int GATHER, int EPI>
__global__ void __launch_bounds__(256)
gemm256(const __half* __restrict__ A, const __half* __restrict__ Wb,
        const float* __restrict__ bb, void* __restrict__ OutV,
        int K, int NW, int ldo)
{
    int e  = blockIdx.z;
    int m0 = blockIdx.y * 128;
    int n0 = blockIdx.x * 256;
    int Mv = NTOK;
    const int* list = d_lists + e * NTOK;
    if (GATHER != 0) { Mv = d_cnt[e]; if (m0 >= Mv) return; }
    const __half* W = Wb + (size_t)e * NW * K;

    extern __shared__ char smem[];
    uint32_t sbase = smem_u32(smem);
    int*   sslot = (int*)(smem + SLOT_OFF);
    float* sBB   = (float*)(smem + BIAS_OFF);

    int tid = threadIdx.x;
    if (tid < 128) {
        int m = m0 + tid;
        sslot[tid] = (GATHER != 0) ? list[m < Mv ? m : Mv - 1] : m;
    }
    sBB[tid] = bb[(size_t)e * NW + n0 + tid];
    __syncthreads();

    const __half* aSrc[4];
    int aRow0 = tid >> 3, cA = tid & 7;
#pragma unroll
    for (int i = 0; i < 4; i++) {
        int row = aRow0 + i * 32;
        int slot = sslot[row];
        aSrc[i] = A + (size_t)slot * K + cA * 8;
    }
    uint32_t dstA0 = (uint32_t)(aRow0 * RS + cA * 16);
    const __half* bBase = W + (size_t)(n0 + aRow0) * K + cA * 8;
    size_t bStep = (size_t)32 * K;
    uint32_t dstB0 = (uint32_t)(ABYTES + aRow0 * RS + cA * 16);

    int wid = tid >> 5, lane = tid & 31;
    int wm = wid & 1, wn = wid >> 1;
    int lr = lane >> 2, lc = lane & 3;
    int mat = lane >> 3, rr = lane & 7;

    uint32_t aOff[4], bOff[4];
#pragma unroll
    for (int mf = 0; mf < 4; mf++)
        aOff[mf] = (uint32_t)((wm * 64 + mf * 16 + (mat & 1) * 8 + rr) * RS + (mat >> 1) * 16);
#pragma unroll
    for (int fp = 0; fp < 4; fp++)
        bOff[fp] = (uint32_t)(ABYTES + (wn * 64 + fp * 16 + (mat >> 1) * 8 + rr) * RS + (mat & 1) * 16);

    float acc[4][8][4] = {};
    int T = K / BK;

    auto issue_tile = [&](int t) {
        uint32_t sb = sbase + (t % NSTAGE) * SSTR;
        int k0 = t * BK;
#pragma unroll
        for (int i = 0; i < 4; i++)
            cp_async16(sb + dstA0 + i * 32 * RS, aSrc[i] + k0);
#pragma unroll
        for (int i = 0; i < 8; i++)
            cp_async16(sb + dstB0 + i * 32 * RS, bBase + i * bStep + k0);
        asm volatile("cp.async.commit_group;" ::: "memory");
    };

    issue_tile(0);
    issue_tile(1);

    for (int t = 0; t < T; t++) {
        asm volatile("cp.async.wait_group 1;" ::: "memory");
        __syncthreads();
        uint32_t sb = sbase + (t % NSTAGE) * SSTR;
#pragma unroll
        for (int kk = 0; kk < 4; kk++) {
            uint32_t koff = kk * 32;
            uint32_t a[4][4];
#pragma unroll
            for (int mf = 0; mf < 4; mf++) ldsm4(a[mf], sb + aOff[mf] + koff);
#pragma unroll
            for (int fp = 0; fp < 4; fp++) {
                uint32_t b[4];
                ldsm4(b, sb + bOff[fp] + koff);
#pragma unroll
                for (int mf = 0; mf < 4; mf++) {
                    mma_f16(acc[mf][2 * fp],     a[mf], b[0], b[1]);
                    mma_f16(acc[mf][2 * fp + 1], a[mf], b[2], b[3]);
                }
            }
        }
        if (t + 2 < T) {
            issue_tile(t + 2);
        } else {
            asm volatile("cp.async.commit_group;" ::: "memory");
        }
    }

#pragma unroll
    for (int mf = 0; mf < 4; mf++) {
#pragma unroll
        for (int half = 0; half < 2; half++) {
            int rt = wm * 64 + mf * 16 + half * 8 + lr;
            int m = m0 + rt;
            if (GATHER != 0 && m >= Mv) continue;
            int orow = sslot[rt];
            float sc = (EPI == 1) ? d_gw[orow] : 0.f;
#pragma unroll
            for (int f = 0; f < 8; f++) {
                int nb = wn * 64 + 8 * f + 2 * lc;
                float c0 = acc[mf][f][half * 2 + 0] + sBB[nb];
                float c1 = acc[mf][f][half * 2 + 1] + sBB[nb + 1];
                if (EPI == 1) {
                    float* O = (float*)OutV;
                    *(float2*)(O + (size_t)orow * ldo + n0 + nb) =
                        make_float2(c0 * sc, c1 * sc);
                } else {
                    const float* y0 = d_ypart + (size_t)(2 * m) * DMODEL + n0 + nb;
                    const float* y1 = y0 + DMODEL;
                    float2 a2 = *(const float2*)y0;
                    float2 b2 = *(const float2*)y1;
                    float* O = (float*)OutV;
                    *(float2*)(O + (size_t)m * ldo + n0 + nb) =
                        make_float2(c0 + a2.x + b2.x, c1 + a2.y + b2.y);
                }
            }
        }
    }
}

// ---------------- launch ----------------
extern "C" void kernel_launch(void* const* d_in, const int* in_sizes, int n_in,
                              void* d_out, int out_size)
{
    const float* x   = (const float*)d_in[0];
    const float* gw  = (const float*)d_in[1];
    const float* eb  = (const float*)d_in[2];
    const float* w1  = (const float*)d_in[3];
    const float* b1  = (const float*)d_in[4];
    const float* w3  = (const float*)d_in[5];
    const float* b3  = (const float*)d_in[6];
    const float* w2  = (const float*)d_in[7];
    const float* b2  = (const float*)d_in[8];
    const float* sw1 = (const float*)d_in[9];
    const float* sb1 = (const float*)d_in[10];
    const float* sw3 = (const float*)d_in[11];
    const float* sb3 = (const float*)d_in[12];
    const float* sw2 = (const float*)d_in[13];
    const float* sb2 = (const float*)d_in[14];
    float* out = (float*)d_out;

    float*  yp_p;  cudaGetSymbolAddress((void**)&yp_p,  d_ypart);
    __half* hx_p;  cudaGetSymbolAddress((void**)&hx_p,  d_hx);
    __half* w1h_p; cudaGetSymbolAddress((void**)&w1h_p, d_w1h);
    __half* w3h_p; cudaGetSymbolAddress((void**)&w3h_p, d_w3h);
    __half* w2h_p; cudaGetSymbolAddress((void**)&w2h_p, d_w2h);
    __half* sw1h_p; cudaGetSymbolAddress((void**)&sw1h_p, d_sw1h);
    __half* sw3h_p; cudaGetSymbolAddress((void**)&sw3h_p, d_sw3h);
    __half* sw2h_p; cudaGetSymbolAddress((void**)&sw2h_p, d_sw2h);
    __half* h_p;   cudaGetSymbolAddress((void**)&h_p,   d_h);
    __half* hs_p;  cudaGetSymbolAddress((void**)&hs_p,  d_hs);

    cudaFuncSetAttribute(gemm_dual<1>, cudaFuncAttributeMaxDynamicSharedMemorySize, SMEM_TOTAL);
    cudaFuncSetAttribute(gemm_dual<0>, cudaFuncAttributeMaxDynamicSharedMemorySize, SMEM_TOTAL);
    cudaFuncSetAttribute(gemm256<2,1>, cudaFuncAttributeMaxDynamicSharedMemorySize, SMEM_TOTAL);
    cudaFuncSetAttribute(gemm256<0,2>, cudaFuncAttributeMaxDynamicSharedMemorySize, SMEM_TOTAL);

    zero_cnt_kernel<<<1, 32>>>();
    gate_kernel<<<(NTOK * 32) / 256, 256>>>(x, gw, eb);

    // merged fp32 -> fp16 conversions (2048 elems per block)
    {
        const int BX  = (int)(((size_t)NTOK * DMODEL) / 2048);        // 4096
        const int BW  = (int)(((size_t)NEXP * DFFE * DMODEL) / 2048); // 4096
        const int BSW = (int)(((size_t)DFFS * DMODEL) / 2048);        // 512
        F2HArgs a;
        a.src[0] = x;   a.dst[0] = hx_p;
        a.src[1] = w1;  a.dst[1] = w1h_p;
        a.src[2] = w3;  a.dst[2] = w3h_p;
        a.src[3] = w2;  a.dst[3] = w2h_p;
        a.src[4] = sw1; a.dst[4] = sw1h_p;
        a.src[5] = sw3; a.dst[5] = sw3h_p;
        a.src[6] = sw2; a.dst[6] = sw2h_p;
        int acc = 0;
        int blks[7] = {BX, BW, BW, BW, BSW, BSW, BSW};
        for (int s = 0; s < 7; s++) { acc += blks[s]; a.blk_end[s] = acc; }
        f2h_all_kernel<<<acc, 256>>>(a);
    }

    // routed stage 1 (fused dual): h = silu(x@W1^T+b1)*(x@W3^T+b3), 128h/CTA
    gemm_dual<1><<<dim3(DFFE / 128, NTOK / 128, NEXP), 256, SMEM_TOTAL>>>(
        hx_p, w1h_p, w3h_p, b1, b3, h_p, DMODEL, DFFE, DFFE);

    // routed stage 2: ypart[slot] = (h@W2^T + b2) * gate_w, 256n/CTA
    gemm256<2,1><<<dim3(DMODEL / 256, NTOK / 128, NEXP), 256, SMEM_TOTAL>>>(
        h_p, w2h_p, b2, yp_p, DFFE, DMODEL, DMODEL);

    // shared stage 1 (fused dual): dense
    gemm_dual<0><<<dim3(DFFS / 128, NTOK / 128, 1), 256, SMEM_TOTAL>>>(
        hx_p, sw1h_p, sw3h_p, sb1, sb3, hs_p, DMODEL, DFFS, DFFS);

    // shared stage 2 + combine: out = hs@sW2^T + sb2 + ypart[2m] + ypart[2m+1]
    gemm256<0,2><<<dim3(DMODEL / 256, NTOK / 128, 1), 256, SMEM_TOTAL>>>(
        hs_p, sw2h_p, sb2, out, DMODEL, DMODEL, DMODEL);
}

// round 13
// speedup vs baseline: 1.2592x; 1.2592x over previous
#include <cuda_runtime.h>
#include <cuda_fp16.h>
#include <cstdint>
#include <math.h>

#define NTOK   8192
#define DMODEL 1024
#define DFFE   512
#define NEXP   16
#define DFFS   1024

// ---------------- scratch (device globals; no allocations) ----------------
__device__ int    d_cnt[NEXP];
__device__ int    d_lists[NEXP * NTOK];
__device__ float  d_gw[2 * NTOK];
__device__ __half d_ypart[(size_t)2 * NTOK * DMODEL];  // routed partials (fp16)
// fp16 operands
__device__ __half d_hx [(size_t)NTOK * DMODEL];
__device__ __half d_w1h[(size_t)NEXP * DFFE * DMODEL];
__device__ __half d_w3h[(size_t)NEXP * DFFE * DMODEL];
__device__ __half d_w2h[(size_t)NEXP * DMODEL * DFFE];
__device__ __half d_sw1h[(size_t)DFFS * DMODEL];
__device__ __half d_sw3h[(size_t)DFFS * DMODEL];
__device__ __half d_sw2h[(size_t)DMODEL * DFFS];
__device__ __half d_h [(size_t)2 * NTOK * DFFE];       // routed hidden (fp16)
__device__ __half d_hs[(size_t)NTOK * DFFS];           // shared hidden (fp16)

__device__ __forceinline__ float fsigmoid(float v) { return 1.f / (1.f + __expf(-v)); }
__device__ __forceinline__ uint32_t smem_u32(const void* p) {
    uint32_t a;
    asm("{ .reg .u64 t; cvta.to.shared.u64 t, %1; cvt.u32.u64 %0, t; }" : "=r"(a) : "l"(p));
    return a;
}
__device__ __forceinline__ void mma_f16(float* c, const uint32_t* a, uint32_t b0, uint32_t b1) {
    asm volatile("mma.sync.aligned.m16n8k16.row.col.f32.f16.f16.f32 "
        "{%0,%1,%2,%3}, {%4,%5,%6,%7}, {%8,%9}, {%0,%1,%2,%3};"
        : "+f"(c[0]), "+f"(c[1]), "+f"(c[2]), "+f"(c[3])
        : "r"(a[0]), "r"(a[1]), "r"(a[2]), "r"(a[3]), "r"(b0), "r"(b1));
}
__device__ __forceinline__ void ldsm4(uint32_t* r, uint32_t addr) {
    asm volatile("ldmatrix.sync.aligned.m8n8.x4.shared.b16 {%0,%1,%2,%3}, [%4];"
        : "=r"(r[0]), "=r"(r[1]), "=r"(r[2]), "=r"(r[3]) : "r"(addr));
}
__device__ __forceinline__ void cp_async16(uint32_t dst, const void* src) {
    asm volatile("cp.async.cg.shared.global [%0], [%1], 16;" :: "r"(dst), "l"(src));
}
__device__ __forceinline__ uint4 pack_h8(float4 u, float4 v) {
    uint4 o;
    half2 h0 = __floats2half2_rn(u.x, u.y);
    half2 h1 = __floats2half2_rn(u.z, u.w);
    half2 h2 = __floats2half2_rn(v.x, v.y);
    half2 h3 = __floats2half2_rn(v.z, v.w);
    o.x = *(uint32_t*)&h0; o.y = *(uint32_t*)&h1;
    o.z = *(uint32_t*)&h2; o.w = *(uint32_t*)&h3;
    return o;
}

// ---------------- smem layout (round-11 proven config) ----------------
#define BK       64
#define RS       144
#define NSTAGE   3
#define BUFBYTES (128 * RS)                    // 18432
#define ABUF_OFF 0
#define BBUF_OFF (NSTAGE * BUFBYTES)           // 55296
#define SLOT_OFF (2 * NSTAGE * BUFBYTES)       // 110592
#define BIAS_OFF (SLOT_OFF + 512)
#define SMEM_TOTAL (BIAS_OFF + 512)            // 111616

// ---------------- prologue: zero counters ----------------
__global__ void zero_cnt_kernel() {
    if (threadIdx.x < NEXP) d_cnt[threadIdx.x] = 0;
}

// ---------------- merged f2h (7 segments) + gate, block-range dispatch ----------------
struct PreArgs {
    const float* src[7];
    __half*      dst[7];
    int          blk_end[7];   // cumulative f2h block counts (2048 elems/block)
};

__device__ void gate_body(int gblk, const float* __restrict__ x,
                          const float* __restrict__ gw,
                          const float* __restrict__ ebias)
{
    int warp = (gblk * 256 + (int)threadIdx.x) >> 5;
    int lane = threadIdx.x & 31;
    if (warp >= NTOK) return;
    const float* xr = x + (size_t)warp * DMODEL;
    float xv[32];
#pragma unroll
    for (int j = 0; j < 32; j++) xv[j] = xr[lane + 32 * j];
    float logits[NEXP];
#pragma unroll
    for (int e = 0; e < NEXP; e++) {
        const float* wr = gw + e * DMODEL;
        float acc = 0.f;
#pragma unroll
        for (int j = 0; j < 32; j++) acc += xv[j] * wr[lane + 32 * j];
#pragma unroll
        for (int o = 16; o > 0; o >>= 1) acc += __shfl_xor_sync(0xffffffffu, acc, o);
        logits[e] = acc;
    }
    if (lane == 0) {
        int i0 = -1, i1 = -1;
        float v0 = -INFINITY, v1 = -INFINITY;
#pragma unroll
        for (int e = 0; e < NEXP; e++) {
            float b = logits[e] + ebias[e];
            if (b > v0) { v1 = v0; i1 = i0; v0 = b; i0 = e; }
            else if (b > v1) { v1 = b; i1 = e; }
        }
        float s0 = fsigmoid(logits[i0]);
        float s1 = fsigmoid(logits[i1]);
        float inv = 1.f / (s0 + s1 + 1e-10f);
        int p0 = atomicAdd(&d_cnt[i0], 1);
        d_lists[i0 * NTOK + p0] = warp * 2 + 0;
        d_gw[warp * 2 + 0] = s0 * inv;
        int p1 = atomicAdd(&d_cnt[i1], 1);
        d_lists[i1 * NTOK + p1] = warp * 2 + 1;
        d_gw[warp * 2 + 1] = s1 * inv;
    }
}

__global__ void pre_kernel(PreArgs args,
                           const float* __restrict__ x,
                           const float* __restrict__ gw,
                           const float* __restrict__ ebias)
{
    int b = blockIdx.x;
    int f2h_total = args.blk_end[6];
    if (b >= f2h_total) {               // gate blocks
        gate_body(b - f2h_total, x, gw, ebias);
        return;
    }
    int seg = 0;
#pragma unroll
    for (int s = 0; s < 7; s++) if (b >= args.blk_end[s]) seg = s + 1;
    int b0 = (seg == 0) ? 0 : args.blk_end[seg - 1];
    size_t i = ((size_t)(b - b0) * blockDim.x + threadIdx.x) * 8;
    const float* src = args.src[seg];
    __half* dst = args.dst[seg];
    float4 a = *(const float4*)(src + i);
    float4 v = *(const float4*)(src + i + 4);
    *(uint4*)(dst + i) = pack_h8(a, v);
}

// ============ merged stage-1: dual-B (W1+W3 interleaved) + SwiGLU ============
// z < NEXP: routed expert z (gather token rows, N=DFFE, out d_h)
// z >= NEXP: shared (dense, N=DFFS, n0 += (z-NEXP)*512, out d_hs)
// CTA: 128 m-rows x 64 h-cols; B tile 128 rows:
//   row r: wn_r=r>>6, half=(r>>5)&1, sub=r&31 -> (W3 if half else W1)[n0+wn_r*32+sub]
// Warp wn: frags 0..3 = W1, 4..7 = W3 of same n -> in-register SwiGLU.
__global__ void __launch_bounds__(256, 2)
gemm_dual_all(const __half* __restrict__ X,
              const __half* __restrict__ w1h, const __half* __restrict__ w3h,
              const float* __restrict__ b1,  const float* __restrict__ b3,
              const __half* __restrict__ sw1h, const __half* __restrict__ sw3h,
              const float* __restrict__ sb1, const float* __restrict__ sb3,
              __half* __restrict__ Hout, __half* __restrict__ HSout)
{
    const int K = DMODEL;
    int z = blockIdx.z;
    bool routed = (z < NEXP);
    int e  = routed ? z : 0;
    int m0 = blockIdx.y * 128;
    int n0 = routed ? blockIdx.x * 64 : ((z - NEXP) * 512 + blockIdx.x * 64);
    int Mv = NTOK;
    const int* list = d_lists + e * NTOK;
    if (routed) { Mv = d_cnt[e]; if (m0 >= Mv) return; }

    const __half* W1 = routed ? (w1h + (size_t)e * DFFE * K) : sw1h;
    const __half* W3 = routed ? (w3h + (size_t)e * DFFE * K) : sw3h;
    const float*  B1 = routed ? (b1 + (size_t)e * DFFE) : sb1;
    const float*  B3 = routed ? (b3 + (size_t)e * DFFE) : sb3;
    __half* Out = routed ? Hout : HSout;
    int ldo = routed ? DFFE : DFFS;

    extern __shared__ char smem[];
    uint32_t sbase = smem_u32(smem);
    int*   sslot = (int*)(smem + SLOT_OFF);
    float* sB1   = (float*)(smem + BIAS_OFF);
    float* sB3   = sB1 + 64;

    int tid = threadIdx.x;
    if (tid < 128) {
        int m = m0 + tid;
        sslot[tid] = routed ? list[m < Mv ? m : Mv - 1] : m;
    } else {
        int j = tid - 128;
        if (j < 64) sB1[j] = B1[n0 + j];
        else        sB3[j - 64] = B3[n0 + j - 64];
    }
    __syncthreads();

    const __half* aSrc[4]; const __half* bSrc[4]; uint32_t dstOff[4];
#pragma unroll
    for (int i = 0; i < 4; i++) {
        int idx = tid + i * 256;            // 0..1023
        int row = idx >> 3, c = idx & 7;
        int slot = sslot[row];
        int ar = routed ? (slot >> 1) : slot;
        aSrc[i] = X + (size_t)ar * K + c * 8;
        int wn_r = row >> 6, half = (row >> 5) & 1, sub = row & 31;
        const __half* Wsel = half ? W3 : W1;
        bSrc[i] = Wsel + (size_t)(n0 + wn_r * 32 + sub) * K + c * 8;
        dstOff[i] = (uint32_t)(row * RS + c * 16);
    }

    int wid = tid >> 5, lane = tid & 31;
    int wm = wid & 3, wn = wid >> 2;
    int lr = lane >> 2, lc = lane & 3;
    int mat = lane >> 3, rr = lane & 7;

    uint32_t aOff[2], bOff[4];
#pragma unroll
    for (int mf = 0; mf < 2; mf++)
        aOff[mf] = (uint32_t)((wm * 32 + mf * 16 + (mat & 1) * 8 + rr) * RS + (mat >> 1) * 16);
#pragma unroll
    for (int fp = 0; fp < 4; fp++)
        bOff[fp] = (uint32_t)((wn * 64 + fp * 16 + (mat >> 1) * 8 + rr) * RS + (mat & 1) * 16);

    float acc[2][8][4] = {};
    const int T = K / BK;

    auto issue_tile = [&](int t) {
        int buf = t % NSTAGE;
        uint32_t aB = sbase + ABUF_OFF + buf * BUFBYTES;
        uint32_t bB = sbase + BBUF_OFF + buf * BUFBYTES;
        int k0 = t * BK;
#pragma unroll
        for (int i = 0; i < 4; i++) {
            cp_async16(aB + dstOff[i], aSrc[i] + k0);
            cp_async16(bB + dstOff[i], bSrc[i] + k0);
        }
        asm volatile("cp.async.commit_group;" ::: "memory");
    };

    issue_tile(0);
    issue_tile(1);

    for (int t = 0; t < T; t++) {
        asm volatile("cp.async.wait_group 1;" ::: "memory");
        __syncthreads();
        uint32_t abuf = sbase + ABUF_OFF + (t % NSTAGE) * BUFBYTES;
        uint32_t bbuf = sbase + BBUF_OFF + (t % NSTAGE) * BUFBYTES;
#pragma unroll
        for (int kk = 0; kk < 4; kk++) {
            uint32_t koff = kk * 32;
            uint32_t a[2][4];
            ldsm4(a[0], abuf + aOff[0] + koff);
            ldsm4(a[1], abuf + aOff[1] + koff);
#pragma unroll
            for (int fp = 0; fp < 4; fp++) {
                uint32_t b[4];
                ldsm4(b, bbuf + bOff[fp] + koff);
                mma_f16(acc[0][2 * fp],     a[0], b[0], b[1]);
                mma_f16(acc[1][2 * fp],     a[1], b[0], b[1]);
                mma_f16(acc[0][2 * fp + 1], a[0], b[2], b[3]);
                mma_f16(acc[1][2 * fp + 1], a[1], b[2], b[3]);
            }
        }
        if (t + 2 < T) {
            issue_tile(t + 2);
        } else {
            asm volatile("cp.async.commit_group;" ::: "memory");
        }
    }

    // fused SwiGLU epilogue
#pragma unroll
    for (int mf = 0; mf < 2; mf++) {
#pragma unroll
        for (int half = 0; half < 2; half++) {
            int rt = wm * 32 + mf * 16 + half * 8 + lr;
            int m = m0 + rt;
            if (routed && m >= Mv) continue;
            int orow = sslot[rt];
#pragma unroll
            for (int f = 0; f < 4; f++) {
                int nl = wn * 32 + 8 * f + 2 * lc;
                float g0 = acc[mf][f][half * 2 + 0] + sB1[nl];
                float g1 = acc[mf][f][half * 2 + 1] + sB1[nl + 1];
                float u0 = acc[mf][f + 4][half * 2 + 0] + sB3[nl];
                float u1 = acc[mf][f + 4][half * 2 + 1] + sB3[nl + 1];
                float h0 = g0 * fsigmoid(g0) * u0;
                float h1 = g1 * fsigmoid(g1) * u1;
                *(half2*)(Out + (size_t)orow * ldo + n0 + nl) = __floats2half2_rn(h0, h1);
            }
        }
    }
}

// ---------------- stage-2 128x128x64 fp16 GEMM, cp.async 3-stage ----------------
// GATHER: 0 dense, 2 gather slot
// EPI: 1 (acc+b)*gw -> ypart(fp16); 2 acc+b+ypart2 -> out(fp32)
template<int GATHER, int EPI>
__global__ void __launch_bounds__(256, 2)
gemm128(const __half* __restrict__ A, const __half* __restrict__ Wb,
        const float* __restrict__ bb, void* __restrict__ OutV,
        int K, int NW, int ldo)
{
    int e  = blockIdx.z;
    int m0 = blockIdx.y * 128;
    int n0 = blockIdx.x * 128;
    int Mv = NTOK;
    const int* list = d_lists + e * NTOK;
    if (GATHER != 0) { Mv = d_cnt[e]; if (m0 >= Mv) return; }
    const __half* W = Wb + (size_t)e * NW * K;

    extern __shared__ char smem[];
    uint32_t sbase = smem_u32(smem);
    int*   sslot = (int*)(smem + SLOT_OFF);
    float* sBB   = (float*)(smem + BIAS_OFF);

    int tid = threadIdx.x;
    if (tid < 128) {
        int m = m0 + tid;
        sslot[tid] = (GATHER != 0) ? list[m < Mv ? m : Mv - 1] : m;
    } else {
        sBB[tid - 128] = bb[(size_t)e * NW + n0 + (tid - 128)];
    }
    __syncthreads();

    const __half* aSrc[4]; const __half* bSrc[4]; uint32_t dstOff[4];
#pragma unroll
    for (int i = 0; i < 4; i++) {
        int idx = tid + i * 256;
        int row = idx >> 3, c = idx & 7;
        int slot = sslot[row];
        aSrc[i] = A + (size_t)slot * K + c * 8;
        bSrc[i] = W + (size_t)(n0 + row) * K + c * 8;
        dstOff[i] = (uint32_t)(row * RS + c * 16);
    }

    int wid = tid >> 5, lane = tid & 31;
    int wm = wid & 3, wn = wid >> 2;
    int lr = lane >> 2, lc = lane & 3;
    int mat = lane >> 3, rr = lane & 7;

    uint32_t aOff[2], bOff[4];
#pragma unroll
    for (int mf = 0; mf < 2; mf++)
        aOff[mf] = (uint32_t)((wm * 32 + mf * 16 + (mat & 1) * 8 + rr) * RS + (mat >> 1) * 16);
#pragma unroll
    for (int fp = 0; fp < 4; fp++)
        bOff[fp] = (uint32_t)((wn * 64 + fp * 16 + (mat >> 1) * 8 + rr) * RS + (mat & 1) * 16);

    float acc[2][8][4] = {};
    int T = K / BK;

    auto issue_tile = [&](int t) {
        int buf = t % NSTAGE;
        uint32_t aB = sbase + ABUF_OFF + buf * BUFBYTES;
        uint32_t bB = sbase + BBUF_OFF + buf * BUFBYTES;
        int k0 = t * BK;
#pragma unroll
        for (int i = 0; i < 4; i++) {
            cp_async16(aB + dstOff[i], aSrc[i] + k0);
            cp_async16(bB + dstOff[i], bSrc[i] + k0);
        }
        asm volatile("cp.async.commit_group;" ::: "memory");
    };

    issue_tile(0);
    issue_tile(1);

    for (int t = 0; t < T; t++) {
        asm volatile("cp.async.wait_group 1;" ::: "memory");
        __syncthreads();
        uint32_t abuf = sbase + ABUF_OFF + (t % NSTAGE) * BUFBYTES;
        uint32_t bbuf = sbase + BBUF_OFF + (t % NSTAGE) * BUFBYTES;
#pragma unroll
        for (int kk = 0; kk < 4; kk++) {
            uint32_t koff = kk * 32;
            uint32_t a[2][4];
            ldsm4(a[0], abuf + aOff[0] + koff);
            ldsm4(a[1], abuf + aOff[1] + koff);
#pragma unroll
            for (int fp = 0; fp < 4; fp++) {
                uint32_t b[4];
                ldsm4(b, bbuf + bOff[fp] + koff);
                mma_f16(acc[0][2 * fp],     a[0], b[0], b[1]);
                mma_f16(acc[1][2 * fp],     a[1], b[0], b[1]);
                mma_f16(acc[0][2 * fp + 1], a[0], b[2], b[3]);
                mma_f16(acc[1][2 * fp + 1], a[1], b[2], b[3]);
            }
        }
        if (t + 2 < T) {
            issue_tile(t + 2);
        } else {
            asm volatile("cp.async.commit_group;" ::: "memory");
        }
    }

#pragma unroll
    for (int mf = 0; mf < 2; mf++) {
#pragma unroll
        for (int half = 0; half < 2; half++) {
            int rt = wm * 32 + mf * 16 + half * 8 + lr;
            int m = m0 + rt;
            if (GATHER != 0 && m >= Mv) continue;
            int orow = sslot[rt];
            float sc = (EPI == 1) ? d_gw[orow] : 0.f;
#pragma unroll
            for (int f = 0; f < 8; f++) {
                int nb = wn * 64 + 8 * f + 2 * lc;
                float c0 = acc[mf][f][half * 2 + 0] + sBB[nb];
                float c1 = acc[mf][f][half * 2 + 1] + sBB[nb + 1];
                if (EPI == 1) {
                    __half* O = (__half*)OutV;
                    *(half2*)(O + (size_t)orow * ldo + n0 + nb) =
                        __floats2half2_rn(c0 * sc, c1 * sc);
                } else {
                    const __half* y0 = d_ypart + (size_t)(2 * m) * DMODEL + n0 + nb;
                    const __half* y1 = y0 + DMODEL;
                    float2 a2 = __half22float2(*(const half2*)y0);
                    float2 b2 = __half22float2(*(const half2*)y1);
                    float* O = (float*)OutV;
                    *(float2*)(O + (size_t)m * ldo + n0 + nb) =
                        make_float2(c0 + a2.x + b2.x, c1 + a2.y + b2.y);
                }
            }
        }
    }
}

// ---------------- launch ----------------
extern "C" void kernel_launch(void* const* d_in, const int* in_sizes, int n_in,
                              void* d_out, int out_size)
{
    const float* x   = (const float*)d_in[0];
    const float* gw  = (const float*)d_in[1];
    const float* eb  = (const float*)d_in[2];
    const float* w1  = (const float*)d_in[3];
    const float* b1  = (const float*)d_in[4];
    const float* w3  = (const float*)d_in[5];
    const float* b3  = (const float*)d_in[6];
    const float* w2  = (const float*)d_in[7];
    const float* b2  = (const float*)d_in[8];
    const float* sw1 = (const float*)d_in[9];
    const float* sb1 = (const float*)d_in[10];
    const float* sw3 = (const float*)d_in[11];
    const float* sb3 = (const float*)d_in[12];
    const float* sw2 = (const float*)d_in[13];
    const float* sb2 = (const float*)d_in[14];
    float* out = (float*)d_out;

    __half* yp_p;  cudaGetSymbolAddress((void**)&yp_p,  d_ypart);
    __half* hx_p;  cudaGetSymbolAddress((void**)&hx_p,  d_hx);
    __half* w1h_p; cudaGetSymbolAddress((void**)&w1h_p, d_w1h);
    __half* w3h_p; cudaGetSymbolAddress((void**)&w3h_p, d_w3h);
    __half* w2h_p; cudaGetSymbolAddress((void**)&w2h_p, d_w2h);
    __half* sw1h_p; cudaGetSymbolAddress((void**)&sw1h_p, d_sw1h);
    __half* sw3h_p; cudaGetSymbolAddress((void**)&sw3h_p, d_sw3h);
    __half* sw2h_p; cudaGetSymbolAddress((void**)&sw2h_p, d_sw2h);
    __half* h_p;   cudaGetSymbolAddress((void**)&h_p,   d_h);
    __half* hs_p;  cudaGetSymbolAddress((void**)&hs_p,  d_hs);

    cudaFuncSetAttribute(gemm_dual_all, cudaFuncAttributeMaxDynamicSharedMemorySize, SMEM_TOTAL);
    cudaFuncSetAttribute(gemm128<2,1>, cudaFuncAttributeMaxDynamicSharedMemorySize, SMEM_TOTAL);
    cudaFuncSetAttribute(gemm128<0,2>, cudaFuncAttributeMaxDynamicSharedMemorySize, SMEM_TOTAL);

    zero_cnt_kernel<<<1, 32>>>();

    // merged f2h (7 segments) + gate
    {
        const int BX  = (int)(((size_t)NTOK * DMODEL) / 2048);        // 4096
        const int BW  = (int)(((size_t)NEXP * DFFE * DMODEL) / 2048); // 4096
        const int BSW = (int)(((size_t)DFFS * DMODEL) / 2048);        // 512
        PreArgs a;
        a.src[0] = x;   a.dst[0] = hx_p;
        a.src[1] = w1;  a.dst[1] = w1h_p;
        a.src[2] = w3;  a.dst[2] = w3h_p;
        a.src[3] = w2;  a.dst[3] = w2h_p;
        a.src[4] = sw1; a.dst[4] = sw1h_p;
        a.src[5] = sw3; a.dst[5] = sw3h_p;
        a.src[6] = sw2; a.dst[6] = sw2h_p;
        int acc = 0;
        int blks[7] = {BX, BW, BW, BW, BSW, BSW, BSW};
        for (int s = 0; s < 7; s++) { acc += blks[s]; a.blk_end[s] = acc; }
        int gate_blocks = (NTOK * 32) / 256;   // 1024
        pre_kernel<<<acc + gate_blocks, 256>>>(a, x, gw, eb);
    }

    // merged stage 1 (routed z=0..15, shared z=16..17)
    gemm_dual_all<<<dim3(DFFE / 64, NTOK / 128, NEXP + 2), 256, SMEM_TOTAL>>>(
        hx_p, w1h_p, w3h_p, b1, b3, sw1h_p, sw3h_p, sb1, sb3, h_p, hs_p);

    // routed stage 2: ypart[slot] = (h@W2^T + b2) * gate_w -> fp16
    gemm128<2,1><<<dim3(DMODEL / 128, NTOK / 128, NEXP), 256, SMEM_TOTAL>>>(
        h_p, w2h_p, b2, yp_p, DFFE, DMODEL, DMODEL);

    // shared stage 2 + combine: out = hs@sW2^T + sb2 + ypart[2m] + ypart[2m+1]
    gemm128<0,2><<<dim3(DMODEL / 128, NTOK / 128, 1), 256, SMEM_TOTAL>>>(
        hs_p, sw2h_p, sb2, out, DMODEL, DMODEL, DMODEL);
}